// round 2
// baseline (speedup 1.0000x reference)
#include <cuda_runtime.h>
#include <math_constants.h>

// RandomFeatures: per (b,k) dilated <=11-tap conv over T positions, then
// masked max + positive-proportion reduction.
//
// Column-form register-blocked version: p = r + m*d; per residue r the conv is
// a stride-1 sliding window in m. Each lane loads NB+KLEN-1 y-values into
// registers and computes NB outputs -> ~0.14 LDS/tap instead of 1.

#define MAX_KLEN 11
#define PADW 512          // left zero halo
#define RPAD 1280         // right zero halo (covers worst-case overshoot, d<=32)
#define WARPS_PER_CTA 8

template<int KLEN, int NB>
__device__ __forceinline__ void conv_block(
    const float* __restrict__ base, int d,
    const float* __restrict__ wreg, float bs,
    int pbase, int ol, int vcnt,
    float& mx, float& cnt)
{
    float Y[NB + KLEN - 1];
#pragma unroll
    for (int t = 0; t < NB + KLEN - 1; t++) Y[t] = base[t * d];
#pragma unroll
    for (int i = 0; i < NB; i++) {
        float a = bs;
#pragma unroll
        for (int j = 0; j < KLEN; j++) a = fmaf(wreg[j], Y[i + j], a);
        int p = pbase + i * d;
        if (i < vcnt && p < ol) {
            mx = fmaxf(mx, a);
            cnt += (a > 0.0f) ? 1.0f : 0.0f;
        }
    }
}

template<int KLEN>
__device__ __forceinline__ void run_warp(
    const float* __restrict__ xs, int lane, int d, int pd, int ol, float bs,
    const float* __restrict__ wreg, int T, float& mx, float& cnt)
{
    int G = 32 / d; if (G < 1) G = 1;          // d <= 32 guaranteed by caller
    int Mmax = (T + d - 1) / d;                // m-values per residue
    int L = (Mmax + G - 1) / G;                // m-values per lane
    int g = lane / d;
    int r = lane - g * d;
    bool active = (g < G);
    if (!active) g = 0;                        // clamp for safe addressing
    int m0 = g * L;
    const float* base = xs + PADW + r - pd + m0 * d;
    int pbase = r + m0 * d;
    int vmax = active ? L : 0;

    conv_block<KLEN, 16>(base, d, wreg, bs, pbase, ol, min(vmax, 16), mx, cnt);
    for (int off = 16; off < L; off += 8) {    // uniform across warp (L uniform)
        conv_block<KLEN, 8>(base + off * d, d, wreg, bs,
                            pbase + off * d, ol, vmax - off, mx, cnt);
    }
}

__global__ void rf_kernel(const float* __restrict__ x,
                          const float* __restrict__ w,
                          const float* __restrict__ bias,
                          const int*   __restrict__ dil,
                          const int*   __restrict__ padr,
                          const int*   __restrict__ olen,
                          float* __restrict__ out,
                          int B, int T, int K) {
    extern __shared__ float xs[];              // PADW + T + RPAD floats, zero halos

    const int b    = blockIdx.y;
    const int lane = threadIdx.x & 31;
    const int warp = threadIdx.x >> 5;
    const int k    = blockIdx.x * WARPS_PER_CTA + warp;

    const int total = PADW + T + RPAD;
    for (int i = threadIdx.x; i < total; i += blockDim.x) {
        int t = i - PADW;
        xs[i] = (t >= 0 && t < T) ? x[(size_t)b * T + t] : 0.0f;
    }
    __syncthreads();

    if (k >= K) return;

    const int   d  = dil[k];
    const int   pd = padr[k];
    const int   ol = olen[k];
    const float bs = bias[k];

    float wreg[MAX_KLEN];
#pragma unroll
    for (int j = 0; j < MAX_KLEN; j++) wreg[j] = __ldg(&w[(size_t)k * MAX_KLEN + j]);

    float mx  = -CUDART_INF_F;
    float cnt = 0.0f;

    if (d >= 1 && d <= 32) {
        // klen inference: taps >= klen are exactly zero (masked at construction).
        if (wreg[10] != 0.0f)
            run_warp<11>(xs, lane, d, pd, ol, bs, wreg, T, mx, cnt);
        else if (wreg[8] != 0.0f)
            run_warp<9>(xs, lane, d, pd, ol, bs, wreg, T, mx, cnt);
        else
            run_warp<7>(xs, lane, d, pd, ol, bs, wreg, T, mx, cnt);
    } else {
        // Safe fallback for out-of-range dilation (not expected for this data).
        for (int p = lane; p < T; p += 32) {
            float a = bs;
#pragma unroll
            for (int j = 0; j < MAX_KLEN; j++) {
                long long idx = (long long)p - pd + (long long)j * d;
                float v = (idx >= 0 && idx < T) ? xs[PADW + (int)idx] : 0.0f;
                a = fmaf(wreg[j], v, a);
            }
            if (p < ol) { mx = fmaxf(mx, a); cnt += (a > 0.0f) ? 1.0f : 0.0f; }
        }
    }

    // Warp reduction over positions.
#pragma unroll
    for (int off = 16; off > 0; off >>= 1) {
        mx   = fmaxf(mx, __shfl_xor_sync(0xFFFFFFFFu, mx, off));
        cnt +=            __shfl_xor_sync(0xFFFFFFFFu, cnt, off);
    }

    if (lane == 0) {
        float* o = out + (size_t)b * 2 * K + 2 * k;
        o[0] = mx;
        o[1] = cnt / (float)ol;
    }
}

extern "C" void kernel_launch(void* const* d_in, const int* in_sizes, int n_in,
                              void* d_out, int out_size) {
    const float* x    = (const float*)d_in[0];
    const float* w    = (const float*)d_in[1];
    const float* bias = (const float*)d_in[2];
    const int*   dil  = (const int*)d_in[3];
    const int*   padr = (const int*)d_in[4];
    const int*   olen = (const int*)d_in[5];
    float* out = (float*)d_out;

    const int K = in_sizes[2];                 // bias element count
    const int B = out_size / (2 * K);
    const int T = in_sizes[0] / B;

    dim3 block(32 * WARPS_PER_CTA);
    dim3 grid((K + WARPS_PER_CTA - 1) / WARPS_PER_CTA, B);
    size_t smem = (size_t)(PADW + T + RPAD) * sizeof(float);

    rf_kernel<<<grid, block, smem>>>(x, w, bias, dil, padr, olen, out, B, T, K);
}